// round 15
// baseline (speedup 1.0000x reference)
#include <cuda_runtime.h>
#include <cuda_fp16.h>
#include <cstdint>

#define NB 4
#define NC 256
#define NH 128
#define NW 128
#define NPIX 16384
#define NHEADS 8
#define NCH 32
#define NSPLIT 32

// ---------------- scratch (static device memory; no allocations) ----------------
__device__ __half g_vf[NB * NC * NPIX];       // v fp16
__device__ __half g_xf[NB * NC * NPIX];       // x fp16
__device__ float g_partial[NSPLIT * NB * NHEADS * NCH * NCH];
__device__ float g_attn[NB * NHEADS * NCH * NCH];
__device__ float g_weff[NC * NC];
__device__ float g_beff[NC];
__device__ __half g_af[NB * NC * 2 * NC];     // A fp16

// ---------------- helpers ----------------
__device__ __forceinline__ unsigned pack_h2(__half a, __half b) {
    __half2 t; t.x = a; t.y = b;
    return *(unsigned*)&t;
}
__device__ __forceinline__ void mma_f16(float* d, const unsigned* a, const unsigned* b) {
    asm volatile(
        "mma.sync.aligned.m16n8k16.row.col.f32.f16.f16.f32 "
        "{%0,%1,%2,%3}, {%4,%5,%6,%7}, {%8,%9}, {%0,%1,%2,%3};"
        : "+f"(d[0]), "+f"(d[1]), "+f"(d[2]), "+f"(d[3])
        : "r"(a[0]), "r"(a[1]), "r"(a[2]), "r"(a[3]), "r"(b[0]), "r"(b[1]));
}
__device__ __forceinline__ void ldsm4(unsigned& d0, unsigned& d1, unsigned& d2, unsigned& d3,
                                      const void* p) {
    unsigned a = (unsigned)__cvta_generic_to_shared(p);
    asm volatile("ldmatrix.sync.aligned.m8n8.x4.shared.b16 {%0,%1,%2,%3},[%4];"
                 : "=r"(d0), "=r"(d1), "=r"(d2), "=r"(d3) : "r"(a));
}
__device__ __forceinline__ void ldsm4t(unsigned& d0, unsigned& d1, unsigned& d2, unsigned& d3,
                                       const void* p) {
    unsigned a = (unsigned)__cvta_generic_to_shared(p);
    asm volatile("ldmatrix.sync.aligned.m8n8.x4.trans.shared.b16 {%0,%1,%2,%3},[%4];"
                 : "=r"(d0), "=r"(d1), "=r"(d2), "=r"(d3) : "r"(a));
}
__device__ __forceinline__ void cpa16(void* s, const void* g) {
    unsigned sa = (unsigned)__cvta_generic_to_shared(s);
    asm volatile("cp.async.cg.shared.global [%0], [%1], 16;" :: "r"(sa), "l"(g));
}

// ---------------- kernel 1: fused dwconv 3x3 + gram partial ----------------
// Block = (bh, sp): head's 32 channels x 512 px (4 image rows).
// Conv from gmem x -> q,k fp16 in smem; v,x fp16 to gmem; then gram MMA from smem.
#define FP 520   // q/k smem pitch in halves (1040B; 1040 mod 128 = 16 -> conflict-free ldmatrix)
#define DG_SMEM (2 * NCH * FP * 2)   // 66560 B

__global__ __launch_bounds__(128) void dwconv_gram(
    const float* __restrict__ x,
    const float* __restrict__ qw, const float* __restrict__ qb,
    const float* __restrict__ kw, const float* __restrict__ kb,
    const float* __restrict__ vw, const float* __restrict__ vb)
{
    extern __shared__ __half sm[];
    __half* qs = sm;
    __half* ks = sm + NCH * FP;

    int bh = blockIdx.x;            // b*8 + h
    int sp = blockIdx.y;            // 0..31 -> rows 4sp..4sp+3
    int b = bh >> 3, h = bh & 7;
    int row0 = sp * 4;
    int tid = threadIdx.x;
    int lane = tid & 31;
    int warp = tid >> 5;

    int i  = row0 + (tid >> 5);          // image row for this thread
    int j0 = (tid & 31) * 4;             // col start
    int lp = tid * 4;                    // local px (0..508)

    // ---- conv phase: 32 channels ----
    for (int cc = 0; cc < NCH; cc++) {
        int c  = h * NCH + cc;
        int bc = b * NC + c;
        const float* xp = x + (size_t)bc * NPIX;

        float wq[9], wk[9], wv[9];
#pragma unroll
        for (int t = 0; t < 9; t++) {
            wq[t] = __ldg(qw + c * 9 + t);
            wk[t] = __ldg(kw + c * 9 + t);
            wv[t] = __ldg(vw + c * 9 + t);
        }
        float bq = __ldg(qb + c), bk = __ldg(kb + c), bv = __ldg(vb + c);

        float l[3][6];
#pragma unroll
        for (int dy = 0; dy < 3; dy++) {
            int ii = i + dy - 1;
            if (ii < 0 || ii >= NH) {
#pragma unroll
                for (int t = 0; t < 6; t++) l[dy][t] = 0.f;
            } else {
                const float* rp = xp + ii * NW;
                l[dy][0] = (j0 > 0) ? __ldg(rp + j0 - 1) : 0.f;
                float4 m = *(const float4*)(rp + j0);
                l[dy][1] = m.x; l[dy][2] = m.y; l[dy][3] = m.z; l[dy][4] = m.w;
                l[dy][5] = (j0 + 4 < NW) ? __ldg(rp + j0 + 4) : 0.f;
            }
        }
        float oq[4], ok[4], ov[4];
#pragma unroll
        for (int e = 0; e < 4; e++) {
            float aq = bq, ak = bk, av = bv;
#pragma unroll
            for (int dy = 0; dy < 3; dy++)
#pragma unroll
                for (int dx = 0; dx < 3; dx++) {
                    float xv = l[dy][e + dx];
                    int t = dy * 3 + dx;
                    aq = fmaf(wq[t], xv, aq);
                    ak = fmaf(wk[t], xv, ak);
                    av = fmaf(wv[t], xv, av);
                }
            oq[e] = aq; ok[e] = ak; ov[e] = av;
        }
        // q,k -> smem (fp16)
        *(uint2*)&qs[cc * FP + lp] = make_uint2(
            pack_h2(__float2half_rn(oq[0]), __float2half_rn(oq[1])),
            pack_h2(__float2half_rn(oq[2]), __float2half_rn(oq[3])));
        *(uint2*)&ks[cc * FP + lp] = make_uint2(
            pack_h2(__float2half_rn(ok[0]), __float2half_rn(ok[1])),
            pack_h2(__float2half_rn(ok[2]), __float2half_rn(ok[3])));
        // v,x -> gmem (fp16, coalesced)
        size_t o = (size_t)bc * NPIX + sp * 512 + lp;
        *(uint2*)(g_vf + o) = make_uint2(
            pack_h2(__float2half_rn(ov[0]), __float2half_rn(ov[1])),
            pack_h2(__float2half_rn(ov[2]), __float2half_rn(ov[3])));
        *(uint2*)(g_xf + o) = make_uint2(
            pack_h2(__float2half_rn(l[1][1]), __float2half_rn(l[1][2])),
            pack_h2(__float2half_rn(l[1][3]), __float2half_rn(l[1][4])));
    }
    __syncthreads();

    // ---- gram phase: S = Q K^T over 512 px (fp16 in, fp32 acc) ----
    float acc[2][4] = {};
    int lr = lane & 15;
    int lc = (lane >> 4) * 8;
    int brow = warp * 8 + (lane & 7);
    int bcol = (lane >> 3) * 8;

    for (int px = 0; px < 512; px += 32) {
        unsigned b4[4];
        ldsm4(b4[0], b4[1], b4[2], b4[3], &ks[brow * FP + px + bcol]);
#pragma unroll
        for (int ks16 = 0; ks16 < 2; ks16++) {
            unsigned a0[4], a1[4];
            ldsm4(a0[0], a0[1], a0[2], a0[3], &qs[lr * FP + px + ks16 * 16 + lc]);
            ldsm4(a1[0], a1[1], a1[2], a1[3], &qs[(16 + lr) * FP + px + ks16 * 16 + lc]);
            mma_f16(acc[0], a0, b4 + ks16 * 2);
            mma_f16(acc[1], a1, b4 + ks16 * 2);
        }
    }

    float* pp = g_partial + ((size_t)sp * NB * NHEADS + bh) * (NCH * NCH);
    int g = lane >> 2, tt = lane & 3;
#pragma unroll
    for (int mt = 0; mt < 2; mt++) {
        int m = mt * 16 + g;
        int n = warp * 8 + tt * 2;
        pp[m * NCH + n]           = acc[mt][0];
        pp[m * NCH + n + 1]       = acc[mt][1];
        pp[(m + 8) * NCH + n]     = acc[mt][2];
        pp[(m + 8) * NCH + n + 1] = acc[mt][3];
    }
}

// ---------------- kernel 3: parallel reduce + softmax (256 thr / bh) ----------------
__global__ __launch_bounds__(256) void softmax_kernel(const float* __restrict__ temperature)
{
    __shared__ float sv[NCH * NCH];

    int bh = blockIdx.x;
    int h = bh & (NHEADS - 1);
    int tid = threadIdx.x;
    int lane = tid & 31;
    int warp = tid >> 5;

    float4 acc = make_float4(0.f, 0.f, 0.f, 0.f);
#pragma unroll 8
    for (int sp = 0; sp < NSPLIT; sp++) {
        const float* p = g_partial + ((size_t)sp * NB * NHEADS + bh) * (NCH * NCH) + tid * 4;
        float4 v = *(const float4*)p;
        acc.x += v.x; acc.y += v.y; acc.z += v.z; acc.w += v.w;
    }
    *(float4*)&sv[tid * 4] = acc;
    __syncthreads();

    float t = temperature[h];
#pragma unroll
    for (int r = 0; r < 4; r++) {
        int row = warp * 4 + r;
        float v = sv[row * NCH + lane] * t;
        float mx = v;
#pragma unroll
        for (int o = 16; o; o >>= 1) mx = fmaxf(mx, __shfl_xor_sync(0xffffffffu, mx, o));
        float e = __expf(v - mx);
        float s = e;
#pragma unroll
        for (int o = 16; o; o >>= 1) s += __shfl_xor_sync(0xffffffffu, s, o);
        g_attn[(size_t)bh * (NCH * NCH) + row * NCH + lane] = e / s;
    }
}

// ---------------- kernel P1: W_eff (32x32 tiles, cp.async pipelined) + parallel b_eff ----------------
__global__ __launch_bounds__(256) void weff_kernel(
    const float* __restrict__ fusion_w, const float* __restrict__ out_w,
    const float* __restrict__ out_b, const float* __restrict__ fusion_b,
    const float* __restrict__ gamma)
{
    __shared__ __align__(16) float Fs[2][32][36];   // [stage][f][k]
    __shared__ __align__(16) float Os[2][32][36];   // [stage][k][c]

    int f0 = (blockIdx.x >> 3) * 32;
    int c0 = (blockIdx.x & 7) * 32;
    int tid = threadIdx.x;
    int tx = tid & 15, ty = tid >> 4;

    auto load_tile = [&](int s, int ko) {
        int row = tid >> 3;
        int kc  = (tid & 7) * 4;
        cpa16(&Fs[s][row][kc], fusion_w + (size_t)(f0 + row) * (2 * NC) + ko + kc);
        cpa16(&Os[s][row][kc], out_w + (size_t)(ko + row) * NC + c0 + kc);
        asm volatile("cp.async.commit_group;");
    };

    load_tile(0, 0);

    // parallel b_eff on the 8 c0==0 blocks: 8 threads per f-row, shfl-reduce
    if ((blockIdx.x & 7) == 0) {
        int fr = tid >> 3;       // 0..31
        int ln = tid & 7;        // 0..7
        int f = f0 + fr;
        float sb = 0.f;
#pragma unroll
        for (int o = ln; o < NC; o += 8)
            sb = fmaf(fusion_w[(size_t)f * 2 * NC + o], out_b[o], sb);
        sb += __shfl_down_sync(0xffffffffu, sb, 4);
        sb += __shfl_down_sync(0xffffffffu, sb, 2);
        sb += __shfl_down_sync(0xffffffffu, sb, 1);
        if (ln == 0) g_beff[f] = gamma[0] * sb + fusion_b[f];
    }

    float acc[2][2] = {};

    for (int it = 0; it < 8; it++) {
        int cur = it & 1;
        if (it + 1 < 8) {
            load_tile(cur ^ 1, (it + 1) * 32);
            asm volatile("cp.async.wait_group 1;");
        } else {
            asm volatile("cp.async.wait_group 0;");
        }
        __syncthreads();
#pragma unroll
        for (int k = 0; k < 32; k++) {
            float fv0 = Fs[cur][ty * 2][k],     fv1 = Fs[cur][ty * 2 + 1][k];
            float ov0 = Os[cur][k][tx * 2],     ov1 = Os[cur][k][tx * 2 + 1];
            acc[0][0] = fmaf(fv0, ov0, acc[0][0]);
            acc[0][1] = fmaf(fv0, ov1, acc[0][1]);
            acc[1][0] = fmaf(fv1, ov0, acc[1][0]);
            acc[1][1] = fmaf(fv1, ov1, acc[1][1]);
        }
        __syncthreads();
    }
    float g = gamma[0];
#pragma unroll
    for (int i = 0; i < 2; i++)
#pragma unroll
        for (int j = 0; j < 2; j++)
            g_weff[(f0 + ty * 2 + i) * NC + c0 + tx * 2 + j] = g * acc[i][j];
}

// ---------------- kernel P2: A_full -> fp16 (smem-staged attn + weff row) ----------------
__global__ __launch_bounds__(512) void afull_kernel(const float* __restrict__ fusion_w)
{
    __shared__ float at[NHEADS * NCH * NCH];
    __shared__ float wr[NC];

    int bf = blockIdx.x;
    int b = bf >> 8, f = bf & 255;
    int col = threadIdx.x;

    const float* ab = g_attn + (size_t)b * NHEADS * NCH * NCH;
#pragma unroll
    for (int r = 0; r < 16; r++)
        at[col + r * 512] = ab[col + r * 512];
    if (col < NC) wr[col] = g_weff[f * NC + col];
    __syncthreads();

    float v;
    if (col < NC) {
        int h = col >> 5, d = col & 31;
        const float* arow = at + (size_t)h * NCH * NCH + d;
        const float* wrow = wr + h * NCH;
        float s = 0.f;
#pragma unroll
        for (int cc = 0; cc < NCH; cc++)
            s = fmaf(wrow[cc], arow[cc * NCH], s);
        v = s;
    } else {
        v = fusion_w[f * 2 * NC + col];
    }
    g_af[(size_t)bf * 2 * NC + col] = __float2half_rn(v);
}

// ---------------- kernel 4: main GEMM — fp16 HMMA, cp.async 2-stage, BK=64 ----------------
#define AP 72     // A smem pitch (halves): 144B rows -> conflict-free ldmatrix
#define BP 136    // B smem pitch (halves): 272B rows -> conflict-free ldmatrix.trans
__global__ __launch_bounds__(256, 2) void main_gemm(float* __restrict__ y)
{
    __shared__ __align__(128) __half As[2][128][AP];
    __shared__ __align__(128) __half Bs[2][64][BP];

    int b  = blockIdx.z;
    int m0 = blockIdx.y * 128;
    int n0 = blockIdx.x * 128;
    int tid  = threadIdx.x;
    int lane = tid & 31;
    int warp = tid >> 5;
    int wm = (warp >> 2) * 64;
    int wn = (warp & 3) * 32;
    int g = lane >> 2;
    int t = lane & 3;

    int lr = lane & 15;
    int lc = (lane >> 4) * 8;

    const __half* gA = g_af + (size_t)(b * NC + m0) * (2 * NC);

    float acc[4][4][4];
#pragma unroll
    for (int i = 0; i < 4; i++)
#pragma unroll
        for (int j = 0; j < 4; j++)
#pragma unroll
            for (int r = 0; r < 4; r++) acc[i][j][r] = 0.f;

    auto load_stage = [&](int s, int it) {
        int k0 = it * 64;
#pragma unroll
        for (int c = 0; c < 4; c++) {
            int id = tid + c * 256;
            int row = id >> 3;
            int kc = (id & 7) * 8;
            cpa16(&As[s][row][kc], gA + (size_t)row * (2 * NC) + k0 + kc);
        }
#pragma unroll
        for (int c = 0; c < 4; c++) {
            int id = tid + c * 256;
            int krow = id >> 4;
            int nc = (id & 15) * 8;
            int grow = k0 + krow;
            const __half* src = (grow < NC)
                ? g_vf + (size_t)(b * NC + grow) * NPIX + n0 + nc
                : g_xf + (size_t)(b * NC + grow - NC) * NPIX + n0 + nc;
            cpa16(&Bs[s][krow][nc], src);
        }
        asm volatile("cp.async.commit_group;");
    };

    load_stage(0, 0);

    const int NIT = (2 * NC) / 64;   // 8
    for (int it = 0; it < NIT; it++) {
        int cur = it & 1;
        if (it + 1 < NIT) {
            load_stage(cur ^ 1, it + 1);
            asm volatile("cp.async.wait_group 1;");
        } else {
            asm volatile("cp.async.wait_group 0;");
        }
        __syncthreads();

#pragma unroll
        for (int ks = 0; ks < 4; ks++) {
            int kof = ks * 16;
            unsigned bh[4][2];
#pragma unroll
            for (int nb = 0; nb < 2; nb++) {
                unsigned d0, d1, d2, d3;
                ldsm4t(d0, d1, d2, d3, &Bs[cur][kof + lr][wn + nb * 16 + lc]);
                bh[nb * 2][0] = d0; bh[nb * 2][1] = d1;
                bh[nb * 2 + 1][0] = d2; bh[nb * 2 + 1][1] = d3;
            }
            unsigned af[4][4];
#pragma unroll
            for (int mf = 0; mf < 4; mf++)
                ldsm4(af[mf][0], af[mf][1], af[mf][2], af[mf][3],
                      &As[cur][wm + mf * 16 + lr][kof + lc]);
#pragma unroll
            for (int nf = 0; nf < 4; nf++)
#pragma unroll
                for (int mf = 0; mf < 4; mf++)
                    mma_f16(acc[mf][nf], af[mf], bh[nf]);
        }
        __syncthreads();
    }

#pragma unroll
    for (int mf = 0; mf < 4; mf++) {
        int m = m0 + wm + mf * 16 + g;
        float be0 = g_beff[m];
        float be1 = g_beff[m + 8];
        float* yr0 = y + (size_t)(b * NC + m) * NPIX + n0 + wn;
        float* yr1 = yr0 + (size_t)8 * NPIX;
#pragma unroll
        for (int nf = 0; nf < 4; nf++) {
            *(float2*)(yr0 + nf * 8 + t * 2) =
                make_float2(acc[mf][nf][0] + be0, acc[mf][nf][1] + be0);
            *(float2*)(yr1 + nf * 8 + t * 2) =
                make_float2(acc[mf][nf][2] + be1, acc[mf][nf][3] + be1);
        }
    }
}

// ---------------- launch ----------------
extern "C" void kernel_launch(void* const* d_in, const int* in_sizes, int n_in,
                              void* d_out, int out_size)
{
    const float* x        = (const float*)d_in[0];
    const float* q_w      = (const float*)d_in[1];
    const float* q_b      = (const float*)d_in[2];
    const float* k_w      = (const float*)d_in[3];
    const float* k_b      = (const float*)d_in[4];
    const float* v_w      = (const float*)d_in[5];
    const float* v_b      = (const float*)d_in[6];
    const float* out_w    = (const float*)d_in[7];
    const float* out_b    = (const float*)d_in[8];
    const float* fusion_w = (const float*)d_in[9];
    const float* fusion_b = (const float*)d_in[10];
    const float* temperature = (const float*)d_in[11];
    const float* gamma    = (const float*)d_in[12];
    float* y = (float*)d_out;

    cudaFuncSetAttribute(dwconv_gram, cudaFuncAttributeMaxDynamicSharedMemorySize, DG_SMEM);

    dim3 dgrid(NB * NHEADS, NSPLIT);
    dwconv_gram<<<dgrid, 128, DG_SMEM>>>(x, q_w, q_b, k_w, k_b, v_w, v_b);

    softmax_kernel<<<NB * NHEADS, 256>>>(temperature);

    weff_kernel<<<64, 256>>>(fusion_w, out_w, out_b, fusion_b, gamma);
    afull_kernel<<<NB * NC, 2 * NC>>>(fusion_w);

    dim3 mgrid(NPIX / 128, NC / 128, NB);
    main_gemm<<<mgrid, 256>>>(y);
}

// round 16
// speedup vs baseline: 1.3049x; 1.3049x over previous
#include <cuda_runtime.h>
#include <cuda_fp16.h>
#include <cstdint>

#define NB 4
#define NC 256
#define NH 128
#define NW 128
#define NPIX 16384
#define NHEADS 8
#define NCH 32
#define NSPLIT 32

// ---------------- scratch (static device memory; no allocations) ----------------
__device__ __half g_qf[NB * NC * NPIX];       // q fp16
__device__ __half g_kf[NB * NC * NPIX];       // k fp16
__device__ __half g_vf[NB * NC * NPIX];       // v fp16
__device__ __half g_xf[NB * NC * NPIX];       // x fp16
__device__ float g_partial[NSPLIT * NB * NHEADS * NCH * NCH];
__device__ float g_attn[NB * NHEADS * NCH * NCH];
__device__ float g_weff[NC * NC];
__device__ float g_beff[NC];
__device__ __half g_af[NB * NC * 2 * NC];     // A fp16

// ---------------- helpers ----------------
__device__ __forceinline__ unsigned pack_h2(__half a, __half b) {
    __half2 t; t.x = a; t.y = b;
    return *(unsigned*)&t;
}
__device__ __forceinline__ void mma_f16(float* d, const unsigned* a, const unsigned* b) {
    asm volatile(
        "mma.sync.aligned.m16n8k16.row.col.f32.f16.f16.f32 "
        "{%0,%1,%2,%3}, {%4,%5,%6,%7}, {%8,%9}, {%0,%1,%2,%3};"
        : "+f"(d[0]), "+f"(d[1]), "+f"(d[2]), "+f"(d[3])
        : "r"(a[0]), "r"(a[1]), "r"(a[2]), "r"(a[3]), "r"(b[0]), "r"(b[1]));
}
__device__ __forceinline__ void ldsm4(unsigned& d0, unsigned& d1, unsigned& d2, unsigned& d3,
                                      const void* p) {
    unsigned a = (unsigned)__cvta_generic_to_shared(p);
    asm volatile("ldmatrix.sync.aligned.m8n8.x4.shared.b16 {%0,%1,%2,%3},[%4];"
                 : "=r"(d0), "=r"(d1), "=r"(d2), "=r"(d3) : "r"(a));
}
__device__ __forceinline__ void ldsm4t(unsigned& d0, unsigned& d1, unsigned& d2, unsigned& d3,
                                       const void* p) {
    unsigned a = (unsigned)__cvta_generic_to_shared(p);
    asm volatile("ldmatrix.sync.aligned.m8n8.x4.trans.shared.b16 {%0,%1,%2,%3},[%4];"
                 : "=r"(d0), "=r"(d1), "=r"(d2), "=r"(d3) : "r"(a));
}
__device__ __forceinline__ void cpa16(void* s, const void* g) {
    unsigned sa = (unsigned)__cvta_generic_to_shared(s);
    asm volatile("cp.async.cg.shared.global [%0], [%1], 16;" :: "r"(sa), "l"(g));
}

// ---------------- kernel 1: dwconv 3x3 -> q,k,v,x all fp16 ----------------
__global__ __launch_bounds__(256) void dwconv_qkv(
    const float* __restrict__ x,
    const float* __restrict__ qw, const float* __restrict__ qb,
    const float* __restrict__ kw, const float* __restrict__ kb,
    const float* __restrict__ vw, const float* __restrict__ vb)
{
    int bc = blockIdx.x;
    int c  = bc & (NC - 1);
    const float* xp = x + (size_t)bc * NPIX;

    float wq[9], wk[9], wv[9];
#pragma unroll
    for (int t = 0; t < 9; t++) {
        wq[t] = qw[c * 9 + t];
        wk[t] = kw[c * 9 + t];
        wv[t] = vw[c * 9 + t];
    }
    float bq = qb[c], bk = kb[c], bv = vb[c];

    for (int p = threadIdx.x; p < NPIX / 4; p += 256) {
        int i  = p >> 5;
        int j0 = (p & 31) * 4;
        float l[3][6];
#pragma unroll
        for (int dy = 0; dy < 3; dy++) {
            int ii = i + dy - 1;
            if (ii < 0 || ii >= NH) {
#pragma unroll
                for (int t = 0; t < 6; t++) l[dy][t] = 0.f;
            } else {
                const float* rp = xp + ii * NW;
                l[dy][0] = (j0 > 0) ? __ldg(rp + j0 - 1) : 0.f;
                float4 m = *(const float4*)(rp + j0);
                l[dy][1] = m.x; l[dy][2] = m.y; l[dy][3] = m.z; l[dy][4] = m.w;
                l[dy][5] = (j0 + 4 < NW) ? __ldg(rp + j0 + 4) : 0.f;
            }
        }
        float oq[4], ok[4], ov[4];
#pragma unroll
        for (int e = 0; e < 4; e++) {
            float aq = bq, ak = bk, av = bv;
#pragma unroll
            for (int dy = 0; dy < 3; dy++)
#pragma unroll
                for (int dx = 0; dx < 3; dx++) {
                    float xv = l[dy][e + dx];
                    int t = dy * 3 + dx;
                    aq = fmaf(wq[t], xv, aq);
                    ak = fmaf(wk[t], xv, ak);
                    av = fmaf(wv[t], xv, av);
                }
            oq[e] = aq; ok[e] = ak; ov[e] = av;
        }
        size_t o = (size_t)bc * NPIX + (size_t)p * 4;
        *(uint2*)(g_qf + o) = make_uint2(
            pack_h2(__float2half_rn(oq[0]), __float2half_rn(oq[1])),
            pack_h2(__float2half_rn(oq[2]), __float2half_rn(oq[3])));
        *(uint2*)(g_kf + o) = make_uint2(
            pack_h2(__float2half_rn(ok[0]), __float2half_rn(ok[1])),
            pack_h2(__float2half_rn(ok[2]), __float2half_rn(ok[3])));
        *(uint2*)(g_vf + o) = make_uint2(
            pack_h2(__float2half_rn(ov[0]), __float2half_rn(ov[1])),
            pack_h2(__float2half_rn(ov[2]), __float2half_rn(ov[3])));
        *(uint2*)(g_xf + o) = make_uint2(
            pack_h2(__float2half_rn(l[1][1]), __float2half_rn(l[1][2])),
            pack_h2(__float2half_rn(l[1][3]), __float2half_rn(l[1][4])));
    }
}

// ---------------- kernel 2: tensor-core gram S = Q K^T (fp16 in, fp32 acc) ----------------
#define QP 72   // smem pitch (halves): 144B rows -> conflict-free ldmatrix
__global__ __launch_bounds__(128) void gram_tc()
{
    __shared__ __align__(128) __half qs[2][NCH][QP];
    __shared__ __align__(128) __half ks[2][NCH][QP];

    int bh = blockIdx.x;
    int sp = blockIdx.y;
    int p0 = sp * (NPIX / NSPLIT);
    int tid = threadIdx.x;
    int lane = tid & 31;
    int warp = tid >> 5;

    const __half* qp = g_qf + (size_t)bh * NCH * NPIX;
    const __half* kp = g_kf + (size_t)bh * NCH * NPIX;

    float acc[2][4] = {};

    auto load_tile = [&](int s, int t0) {
#pragma unroll
        for (int r = 0; r < 2; r++) {
            int id = tid + r * 128;
            int ch = id >> 3;
            int pc = id & 7;
            cpa16(&qs[s][ch][pc * 8], qp + (size_t)ch * NPIX + t0 + pc * 8);
            cpa16(&ks[s][ch][pc * 8], kp + (size_t)ch * NPIX + t0 + pc * 8);
        }
        asm volatile("cp.async.commit_group;");
    };

    load_tile(0, p0);

    int lr = lane & 15;
    int lc = (lane >> 4) * 8;
    int brow = warp * 8 + (lane & 7);
    int bcol = (lane >> 3) * 8;

    for (int t = 0; t < 8; t++) {
        int cur = t & 1;
        if (t + 1 < 8) {
            load_tile(cur ^ 1, p0 + (t + 1) * 64);
            asm volatile("cp.async.wait_group 1;");
        } else {
            asm volatile("cp.async.wait_group 0;");
        }
        __syncthreads();

#pragma unroll
        for (int s2 = 0; s2 < 2; s2++) {
            int px = s2 * 32;
            unsigned b4[4];
            ldsm4(b4[0], b4[1], b4[2], b4[3], &ks[cur][brow][px + bcol]);
#pragma unroll
            for (int ks16 = 0; ks16 < 2; ks16++) {
                unsigned a0[4], a1[4];
                ldsm4(a0[0], a0[1], a0[2], a0[3], &qs[cur][lr][px + ks16 * 16 + lc]);
                ldsm4(a1[0], a1[1], a1[2], a1[3], &qs[cur][16 + lr][px + ks16 * 16 + lc]);
                mma_f16(acc[0], a0, b4 + ks16 * 2);
                mma_f16(acc[1], a1, b4 + ks16 * 2);
            }
        }
        __syncthreads();
    }

    float* pp = g_partial + ((size_t)sp * NB * NHEADS + bh) * (NCH * NCH);
    int g = lane >> 2, tt = lane & 3;
#pragma unroll
    for (int mt = 0; mt < 2; mt++) {
        int m = mt * 16 + g;
        int n = warp * 8 + tt * 2;
        pp[m * NCH + n]           = acc[mt][0];
        pp[m * NCH + n + 1]       = acc[mt][1];
        pp[(m + 8) * NCH + n]     = acc[mt][2];
        pp[(m + 8) * NCH + n + 1] = acc[mt][3];
    }
}

// ---------------- kernel 3: merged softmax (blocks 0..31) + weff/b_eff (blocks 32..95) ----------------
__global__ __launch_bounds__(256) void mid_kernel(
    const float* __restrict__ temperature,
    const float* __restrict__ fusion_w, const float* __restrict__ out_w,
    const float* __restrict__ out_b, const float* __restrict__ fusion_b,
    const float* __restrict__ gamma)
{
    __shared__ __align__(16) float Fs[2][32][36];
    __shared__ __align__(16) float Os[2][32][36];
    __shared__ float sv[NCH * NCH];

    int bid = blockIdx.x;
    int tid = threadIdx.x;
    int lane = tid & 31;
    int warp = tid >> 5;

    if (bid < 32) {
        // ---- softmax for bh = bid ----
        int bh = bid;
        int h = bh & (NHEADS - 1);

        float4 acc = make_float4(0.f, 0.f, 0.f, 0.f);
#pragma unroll 8
        for (int sp = 0; sp < NSPLIT; sp++) {
            const float* p = g_partial + ((size_t)sp * NB * NHEADS + bh) * (NCH * NCH) + tid * 4;
            float4 v = *(const float4*)p;
            acc.x += v.x; acc.y += v.y; acc.z += v.z; acc.w += v.w;
        }
        *(float4*)&sv[tid * 4] = acc;
        __syncthreads();

        float t = temperature[h];
#pragma unroll
        for (int r = 0; r < 4; r++) {
            int row = warp * 4 + r;
            float v = sv[row * NCH + lane] * t;
            float mx = v;
#pragma unroll
            for (int o = 16; o; o >>= 1) mx = fmaxf(mx, __shfl_xor_sync(0xffffffffu, mx, o));
            float e = __expf(v - mx);
            float s = e;
#pragma unroll
            for (int o = 16; o; o >>= 1) s += __shfl_xor_sync(0xffffffffu, s, o);
            g_attn[(size_t)bh * (NCH * NCH) + row * NCH + lane] = e / s;
        }
        return;
    }

    // ---- weff tile for wb = bid - 32 ----
    int wb = bid - 32;
    int f0 = (wb >> 3) * 32;
    int c0 = (wb & 7) * 32;
    int tx = tid & 15, ty = tid >> 4;

    auto load_tile = [&](int s, int ko) {
        int row = tid >> 3;
        int kc  = (tid & 7) * 4;
        cpa16(&Fs[s][row][kc], fusion_w + (size_t)(f0 + row) * (2 * NC) + ko + kc);
        cpa16(&Os[s][row][kc], out_w + (size_t)(ko + row) * NC + c0 + kc);
        asm volatile("cp.async.commit_group;");
    };

    load_tile(0, 0);

    // parallel b_eff on the c0==0 blocks: 8 threads per f-row, shfl-reduce
    if ((wb & 7) == 0) {
        int fr = tid >> 3;
        int ln = tid & 7;
        int f = f0 + fr;
        float sb = 0.f;
#pragma unroll
        for (int o = ln; o < NC; o += 8)
            sb = fmaf(fusion_w[(size_t)f * 2 * NC + o], out_b[o], sb);
        sb += __shfl_down_sync(0xffffffffu, sb, 4);
        sb += __shfl_down_sync(0xffffffffu, sb, 2);
        sb += __shfl_down_sync(0xffffffffu, sb, 1);
        if (ln == 0) g_beff[f] = gamma[0] * sb + fusion_b[f];
    }

    float acc[2][2] = {};

    for (int it = 0; it < 8; it++) {
        int cur = it & 1;
        if (it + 1 < 8) {
            load_tile(cur ^ 1, (it + 1) * 32);
            asm volatile("cp.async.wait_group 1;");
        } else {
            asm volatile("cp.async.wait_group 0;");
        }
        __syncthreads();
#pragma unroll
        for (int k = 0; k < 32; k++) {
            float fv0 = Fs[cur][ty * 2][k],     fv1 = Fs[cur][ty * 2 + 1][k];
            float ov0 = Os[cur][k][tx * 2],     ov1 = Os[cur][k][tx * 2 + 1];
            acc[0][0] = fmaf(fv0, ov0, acc[0][0]);
            acc[0][1] = fmaf(fv0, ov1, acc[0][1]);
            acc[1][0] = fmaf(fv1, ov0, acc[1][0]);
            acc[1][1] = fmaf(fv1, ov1, acc[1][1]);
        }
        __syncthreads();
    }
    float g = gamma[0];
#pragma unroll
    for (int i = 0; i < 2; i++)
#pragma unroll
        for (int j = 0; j < 2; j++)
            g_weff[(f0 + ty * 2 + i) * NC + c0 + tx * 2 + j] = g * acc[i][j];
}

// ---------------- kernel P2: A_full -> fp16 (16 f-rows per block; attn staged once) ----------------
__global__ __launch_bounds__(512) void afull_kernel(const float* __restrict__ fusion_w)
{
    __shared__ float at[NHEADS * NCH * NCH];   // 32 KB
    __shared__ float wr[16 * NC];              // 16 KB

    int b  = blockIdx.x >> 4;
    int fg = (blockIdx.x & 15) * 16;
    int tid = threadIdx.x;

    const float* ab = g_attn + (size_t)b * NHEADS * NCH * NCH;
#pragma unroll
    for (int r = 0; r < 16; r++)
        at[tid + r * 512] = ab[tid + r * 512];
#pragma unroll
    for (int r = 0; r < 8; r++)
        wr[tid + r * 512] = g_weff[(size_t)fg * NC + tid + r * 512];
    __syncthreads();

    int col = tid;
    if (col < NC) {
        int h = col >> 5, d = col & 31;
        const float* arow = at + (size_t)h * NCH * NCH + d;
#pragma unroll
        for (int fi = 0; fi < 16; fi++) {
            const float* wrow = wr + fi * NC + h * NCH;
            float s = 0.f;
#pragma unroll
            for (int cc = 0; cc < NCH; cc++)
                s = fmaf(wrow[cc], arow[cc * NCH], s);
            g_af[((size_t)(b * NC + fg + fi)) * (2 * NC) + col] = __float2half_rn(s);
        }
    } else {
#pragma unroll
        for (int fi = 0; fi < 16; fi++) {
            float v = fusion_w[(size_t)(fg + fi) * (2 * NC) + col];
            g_af[((size_t)(b * NC + fg + fi)) * (2 * NC) + col] = __float2half_rn(v);
        }
    }
}

// ---------------- kernel 4: main GEMM — fp16 HMMA, cp.async 2-stage, BK=64 ----------------
#define AP 72     // A smem pitch (halves): 144B rows -> conflict-free ldmatrix
#define BP 136    // B smem pitch (halves): 272B rows -> conflict-free ldmatrix.trans
__global__ __launch_bounds__(256, 2) void main_gemm(float* __restrict__ y)
{
    __shared__ __align__(128) __half As[2][128][AP];
    __shared__ __align__(128) __half Bs[2][64][BP];

    int b  = blockIdx.z;
    int m0 = blockIdx.y * 128;
    int n0 = blockIdx.x * 128;
    int tid  = threadIdx.x;
    int lane = tid & 31;
    int warp = tid >> 5;
    int wm = (warp >> 2) * 64;
    int wn = (warp & 3) * 32;
    int g = lane >> 2;
    int t = lane & 3;

    int lr = lane & 15;
    int lc = (lane >> 4) * 8;

    const __half* gA = g_af + (size_t)(b * NC + m0) * (2 * NC);

    float acc[4][4][4];
#pragma unroll
    for (int i = 0; i < 4; i++)
#pragma unroll
        for (int j = 0; j < 4; j++)
#pragma unroll
            for (int r = 0; r < 4; r++) acc[i][j][r] = 0.f;

    auto load_stage = [&](int s, int it) {
        int k0 = it * 64;
#pragma unroll
        for (int c = 0; c < 4; c++) {
            int id = tid + c * 256;
            int row = id >> 3;
            int kc = (id & 7) * 8;
            cpa16(&As[s][row][kc], gA + (size_t)row * (2 * NC) + k0 + kc);
        }
#pragma unroll
        for (int c = 0; c < 4; c++) {
            int id = tid + c * 256;
            int krow = id >> 4;
            int nc = (id & 15) * 8;
            int grow = k0 + krow;
            const __half* src = (grow < NC)
                ? g_vf + (size_t)(b * NC + grow) * NPIX + n0 + nc
                : g_xf + (size_t)(b * NC + grow - NC) * NPIX + n0 + nc;
            cpa16(&Bs[s][krow][nc], src);
        }
        asm volatile("cp.async.commit_group;");
    };

    load_stage(0, 0);

    const int NIT = (2 * NC) / 64;   // 8
    for (int it = 0; it < NIT; it++) {
        int cur = it & 1;
        if (it + 1 < NIT) {
            load_stage(cur ^ 1, it + 1);
            asm volatile("cp.async.wait_group 1;");
        } else {
            asm volatile("cp.async.wait_group 0;");
        }
        __syncthreads();

#pragma unroll
        for (int ks = 0; ks < 4; ks++) {
            int kof = ks * 16;
            unsigned bh[4][2];
#pragma unroll
            for (int nb = 0; nb < 2; nb++) {
                unsigned d0, d1, d2, d3;
                ldsm4t(d0, d1, d2, d3, &Bs[cur][kof + lr][wn + nb * 16 + lc]);
                bh[nb * 2][0] = d0; bh[nb * 2][1] = d1;
                bh[nb * 2 + 1][0] = d2; bh[nb * 2 + 1][1] = d3;
            }
            unsigned af[4][4];
#pragma unroll
            for (int mf = 0; mf < 4; mf++)
                ldsm4(af[mf][0], af[mf][1], af[mf][2], af[mf][3],
                      &As[cur][wm + mf * 16 + lr][kof + lc]);
#pragma unroll
            for (int nf = 0; nf < 4; nf++)
#pragma unroll
                for (int mf = 0; mf < 4; mf++)
                    mma_f16(acc[mf][nf], af[mf], bh[nf]);
        }
        __syncthreads();
    }

#pragma unroll
    for (int mf = 0; mf < 4; mf++) {
        int m = m0 + wm + mf * 16 + g;
        float be0 = g_beff[m];
        float be1 = g_beff[m + 8];
        float* yr0 = y + (size_t)(b * NC + m) * NPIX + n0 + wn;
        float* yr1 = yr0 + (size_t)8 * NPIX;
#pragma unroll
        for (int nf = 0; nf < 4; nf++) {
            *(float2*)(yr0 + nf * 8 + t * 2) =
                make_float2(acc[mf][nf][0] + be0, acc[mf][nf][1] + be0);
            *(float2*)(yr1 + nf * 8 + t * 2) =
                make_float2(acc[mf][nf][2] + be1, acc[mf][nf][3] + be1);
        }
    }
}

// ---------------- launch ----------------
extern "C" void kernel_launch(void* const* d_in, const int* in_sizes, int n_in,
                              void* d_out, int out_size)
{
    const float* x        = (const float*)d_in[0];
    const float* q_w      = (const float*)d_in[1];
    const float* q_b      = (const float*)d_in[2];
    const float* k_w      = (const float*)d_in[3];
    const float* k_b      = (const float*)d_in[4];
    const float* v_w      = (const float*)d_in[5];
    const float* v_b      = (const float*)d_in[6];
    const float* out_w    = (const float*)d_in[7];
    const float* out_b    = (const float*)d_in[8];
    const float* fusion_w = (const float*)d_in[9];
    const float* fusion_b = (const float*)d_in[10];
    const float* temperature = (const float*)d_in[11];
    const float* gamma    = (const float*)d_in[12];
    float* y = (float*)d_out;

    dwconv_qkv<<<NB * NC, 256>>>(x, q_w, q_b, k_w, k_b, v_w, v_b);

    dim3 ggrid(NB * NHEADS, NSPLIT);
    gram_tc<<<ggrid, 128>>>();

    mid_kernel<<<96, 256>>>(temperature, fusion_w, out_w, out_b, fusion_b, gamma);

    afull_kernel<<<NB * 16, 512>>>(fusion_w);

    dim3 mgrid(NPIX / 128, NC / 128, NB);
    main_gemm<<<mgrid, 256>>>(y);
}

// round 17
// speedup vs baseline: 1.3323x; 1.0210x over previous
#include <cuda_runtime.h>
#include <cuda_fp16.h>
#include <cstdint>

#define NB 4
#define NC 256
#define NH 128
#define NW 128
#define NPIX 16384
#define NHEADS 8
#define NCH 32
#define NSPLIT 32

// ---------------- scratch (static device memory; no allocations) ----------------
__device__ __half g_qf[NB * NC * NPIX];       // q fp16
__device__ __half g_kf[NB * NC * NPIX];       // k fp16
__device__ __half g_vf[NB * NC * NPIX];       // v fp16
__device__ __half g_xf[NB * NC * NPIX];       // x fp16
__device__ float g_partial[NSPLIT * NB * NHEADS * NCH * NCH];
__device__ float g_attn[NB * NHEADS * NCH * NCH];
__device__ float g_weff[NC * NC];
__device__ float g_beff[NC];
__device__ __half g_af[NB * NC * 2 * NC];     // A fp16

// ---------------- helpers ----------------
__device__ __forceinline__ unsigned pack_h2(__half a, __half b) {
    __half2 t; t.x = a; t.y = b;
    return *(unsigned*)&t;
}
__device__ __forceinline__ unsigned h2u(__half2 v) { return *(unsigned*)&v; }
__device__ __forceinline__ void mma_f16(float* d, const unsigned* a, const unsigned* b) {
    asm volatile(
        "mma.sync.aligned.m16n8k16.row.col.f32.f16.f16.f32 "
        "{%0,%1,%2,%3}, {%4,%5,%6,%7}, {%8,%9}, {%0,%1,%2,%3};"
        : "+f"(d[0]), "+f"(d[1]), "+f"(d[2]), "+f"(d[3])
        : "r"(a[0]), "r"(a[1]), "r"(a[2]), "r"(a[3]), "r"(b[0]), "r"(b[1]));
}
__device__ __forceinline__ void ldsm4(unsigned& d0, unsigned& d1, unsigned& d2, unsigned& d3,
                                      const void* p) {
    unsigned a = (unsigned)__cvta_generic_to_shared(p);
    asm volatile("ldmatrix.sync.aligned.m8n8.x4.shared.b16 {%0,%1,%2,%3},[%4];"
                 : "=r"(d0), "=r"(d1), "=r"(d2), "=r"(d3) : "r"(a));
}
__device__ __forceinline__ void ldsm4t(unsigned& d0, unsigned& d1, unsigned& d2, unsigned& d3,
                                       const void* p) {
    unsigned a = (unsigned)__cvta_generic_to_shared(p);
    asm volatile("ldmatrix.sync.aligned.m8n8.x4.trans.shared.b16 {%0,%1,%2,%3},[%4];"
                 : "=r"(d0), "=r"(d1), "=r"(d2), "=r"(d3) : "r"(a));
}
__device__ __forceinline__ void cpa16(void* s, const void* g) {
    unsigned sa = (unsigned)__cvta_generic_to_shared(s);
    asm volatile("cp.async.cg.shared.global [%0], [%1], 16;" :: "r"(sa), "l"(g));
}

// ---------------- kernel 1: dwconv 3x3 (half2 math) -> q,k,v,x all fp16 ----------------
__global__ __launch_bounds__(256) void dwconv_qkv(
    const float* __restrict__ x,
    const float* __restrict__ qw, const float* __restrict__ qb,
    const float* __restrict__ kw, const float* __restrict__ kb,
    const float* __restrict__ vw, const float* __restrict__ vb)
{
    int bc = blockIdx.x;
    int c  = bc & (NC - 1);
    const float* xp = x + (size_t)bc * NPIX;

    __half2 wq2[9], wk2[9], wv2[9];
#pragma unroll
    for (int t = 0; t < 9; t++) {
        wq2[t] = __float2half2_rn(qw[c * 9 + t]);
        wk2[t] = __float2half2_rn(kw[c * 9 + t]);
        wv2[t] = __float2half2_rn(vw[c * 9 + t]);
    }
    __half2 bq2 = __float2half2_rn(qb[c]);
    __half2 bk2 = __float2half2_rn(kb[c]);
    __half2 bv2 = __float2half2_rn(vb[c]);

    for (int p = threadIdx.x; p < NPIX / 4; p += 256) {
        int i  = p >> 5;
        int j0 = (p & 31) * 4;
        float l[3][6];
#pragma unroll
        for (int dy = 0; dy < 3; dy++) {
            int ii = i + dy - 1;
            if (ii < 0 || ii >= NH) {
#pragma unroll
                for (int t = 0; t < 6; t++) l[dy][t] = 0.f;
            } else {
                const float* rp = xp + ii * NW;
                l[dy][0] = (j0 > 0) ? __ldg(rp + j0 - 1) : 0.f;
                float4 m = *(const float4*)(rp + j0);
                l[dy][1] = m.x; l[dy][2] = m.y; l[dy][3] = m.z; l[dy][4] = m.w;
                l[dy][5] = (j0 + 4 < NW) ? __ldg(rp + j0 + 4) : 0.f;
            }
        }
        // packed windows: hw[dy][t] = (l[t], l[t+1]); pair0 tap dx -> hw[dx], pair1 -> hw[dx+2]
        __half2 hw[3][5];
#pragma unroll
        for (int dy = 0; dy < 3; dy++)
#pragma unroll
            for (int t = 0; t < 5; t++)
                hw[dy][t] = __floats2half2_rn(l[dy][t], l[dy][t + 1]);

        __half2 aq0 = bq2, aq1 = bq2;
        __half2 ak0 = bk2, ak1 = bk2;
        __half2 av0 = bv2, av1 = bv2;
#pragma unroll
        for (int dy = 0; dy < 3; dy++)
#pragma unroll
            for (int dx = 0; dx < 3; dx++) {
                int t = dy * 3 + dx;
                aq0 = __hfma2(wq2[t], hw[dy][dx],     aq0);
                aq1 = __hfma2(wq2[t], hw[dy][dx + 2], aq1);
                ak0 = __hfma2(wk2[t], hw[dy][dx],     ak0);
                ak1 = __hfma2(wk2[t], hw[dy][dx + 2], ak1);
                av0 = __hfma2(wv2[t], hw[dy][dx],     av0);
                av1 = __hfma2(wv2[t], hw[dy][dx + 2], av1);
            }

        size_t o = (size_t)bc * NPIX + (size_t)p * 4;
        *(uint2*)(g_qf + o) = make_uint2(h2u(aq0), h2u(aq1));
        *(uint2*)(g_kf + o) = make_uint2(h2u(ak0), h2u(ak1));
        *(uint2*)(g_vf + o) = make_uint2(h2u(av0), h2u(av1));
        *(uint2*)(g_xf + o) = make_uint2(
            pack_h2(__float2half_rn(l[1][1]), __float2half_rn(l[1][2])),
            pack_h2(__float2half_rn(l[1][3]), __float2half_rn(l[1][4])));
    }
}

// ---------------- kernel 2: tensor-core gram S = Q K^T (fp16 in, fp32 acc) ----------------
#define QP 72   // smem pitch (halves): 144B rows -> conflict-free ldmatrix
__global__ __launch_bounds__(128) void gram_tc()
{
    __shared__ __align__(128) __half qs[2][NCH][QP];
    __shared__ __align__(128) __half ks[2][NCH][QP];

    int bh = blockIdx.x;
    int sp = blockIdx.y;
    int p0 = sp * (NPIX / NSPLIT);
    int tid = threadIdx.x;
    int lane = tid & 31;
    int warp = tid >> 5;

    const __half* qp = g_qf + (size_t)bh * NCH * NPIX;
    const __half* kp = g_kf + (size_t)bh * NCH * NPIX;

    float acc[2][4] = {};

    auto load_tile = [&](int s, int t0) {
#pragma unroll
        for (int r = 0; r < 2; r++) {
            int id = tid + r * 128;
            int ch = id >> 3;
            int pc = id & 7;
            cpa16(&qs[s][ch][pc * 8], qp + (size_t)ch * NPIX + t0 + pc * 8);
            cpa16(&ks[s][ch][pc * 8], kp + (size_t)ch * NPIX + t0 + pc * 8);
        }
        asm volatile("cp.async.commit_group;");
    };

    load_tile(0, p0);

    int lr = lane & 15;
    int lc = (lane >> 4) * 8;
    int brow = warp * 8 + (lane & 7);
    int bcol = (lane >> 3) * 8;

    for (int t = 0; t < 8; t++) {
        int cur = t & 1;
        if (t + 1 < 8) {
            load_tile(cur ^ 1, p0 + (t + 1) * 64);
            asm volatile("cp.async.wait_group 1;");
        } else {
            asm volatile("cp.async.wait_group 0;");
        }
        __syncthreads();

#pragma unroll
        for (int s2 = 0; s2 < 2; s2++) {
            int px = s2 * 32;
            unsigned b4[4];
            ldsm4(b4[0], b4[1], b4[2], b4[3], &ks[cur][brow][px + bcol]);
#pragma unroll
            for (int ks16 = 0; ks16 < 2; ks16++) {
                unsigned a0[4], a1[4];
                ldsm4(a0[0], a0[1], a0[2], a0[3], &qs[cur][lr][px + ks16 * 16 + lc]);
                ldsm4(a1[0], a1[1], a1[2], a1[3], &qs[cur][16 + lr][px + ks16 * 16 + lc]);
                mma_f16(acc[0], a0, b4 + ks16 * 2);
                mma_f16(acc[1], a1, b4 + ks16 * 2);
            }
        }
        __syncthreads();
    }

    float* pp = g_partial + ((size_t)sp * NB * NHEADS + bh) * (NCH * NCH);
    int g = lane >> 2, tt = lane & 3;
#pragma unroll
    for (int mt = 0; mt < 2; mt++) {
        int m = mt * 16 + g;
        int n = warp * 8 + tt * 2;
        pp[m * NCH + n]           = acc[mt][0];
        pp[m * NCH + n + 1]       = acc[mt][1];
        pp[(m + 8) * NCH + n]     = acc[mt][2];
        pp[(m + 8) * NCH + n + 1] = acc[mt][3];
    }
}

// ---------------- kernel 3: merged softmax (blocks 0..31) + weff/b_eff (blocks 32..95) ----------------
__global__ __launch_bounds__(256) void mid_kernel(
    const float* __restrict__ temperature,
    const float* __restrict__ fusion_w, const float* __restrict__ out_w,
    const float* __restrict__ out_b, const float* __restrict__ fusion_b,
    const float* __restrict__ gamma)
{
    __shared__ __align__(16) float Fs[2][32][36];
    __shared__ __align__(16) float Os[2][32][36];
    __shared__ float sv[NCH * NCH];

    int bid = blockIdx.x;
    int tid = threadIdx.x;
    int lane = tid & 31;
    int warp = tid >> 5;

    if (bid < 32) {
        int bh = bid;
        int h = bh & (NHEADS - 1);

        float4 acc = make_float4(0.f, 0.f, 0.f, 0.f);
#pragma unroll 8
        for (int sp = 0; sp < NSPLIT; sp++) {
            const float* p = g_partial + ((size_t)sp * NB * NHEADS + bh) * (NCH * NCH) + tid * 4;
            float4 v = *(const float4*)p;
            acc.x += v.x; acc.y += v.y; acc.z += v.z; acc.w += v.w;
        }
        *(float4*)&sv[tid * 4] = acc;
        __syncthreads();

        float t = temperature[h];
#pragma unroll
        for (int r = 0; r < 4; r++) {
            int row = warp * 4 + r;
            float v = sv[row * NCH + lane] * t;
            float mx = v;
#pragma unroll
            for (int o = 16; o; o >>= 1) mx = fmaxf(mx, __shfl_xor_sync(0xffffffffu, mx, o));
            float e = __expf(v - mx);
            float s = e;
#pragma unroll
            for (int o = 16; o; o >>= 1) s += __shfl_xor_sync(0xffffffffu, s, o);
            g_attn[(size_t)bh * (NCH * NCH) + row * NCH + lane] = e / s;
        }
        return;
    }

    int wb = bid - 32;
    int f0 = (wb >> 3) * 32;
    int c0 = (wb & 7) * 32;
    int tx = tid & 15, ty = tid >> 4;

    auto load_tile = [&](int s, int ko) {
        int row = tid >> 3;
        int kc  = (tid & 7) * 4;
        cpa16(&Fs[s][row][kc], fusion_w + (size_t)(f0 + row) * (2 * NC) + ko + kc);
        cpa16(&Os[s][row][kc], out_w + (size_t)(ko + row) * NC + c0 + kc);
        asm volatile("cp.async.commit_group;");
    };

    load_tile(0, 0);

    if ((wb & 7) == 0) {
        int fr = tid >> 3;
        int ln = tid & 7;
        int f = f0 + fr;
        float sb = 0.f;
#pragma unroll
        for (int o = ln; o < NC; o += 8)
            sb = fmaf(fusion_w[(size_t)f * 2 * NC + o], out_b[o], sb);
        sb += __shfl_down_sync(0xffffffffu, sb, 4);
        sb += __shfl_down_sync(0xffffffffu, sb, 2);
        sb += __shfl_down_sync(0xffffffffu, sb, 1);
        if (ln == 0) g_beff[f] = gamma[0] * sb + fusion_b[f];
    }

    float acc[2][2] = {};

    for (int it = 0; it < 8; it++) {
        int cur = it & 1;
        if (it + 1 < 8) {
            load_tile(cur ^ 1, (it + 1) * 32);
            asm volatile("cp.async.wait_group 1;");
        } else {
            asm volatile("cp.async.wait_group 0;");
        }
        __syncthreads();
#pragma unroll
        for (int k = 0; k < 32; k++) {
            float fv0 = Fs[cur][ty * 2][k],     fv1 = Fs[cur][ty * 2 + 1][k];
            float ov0 = Os[cur][k][tx * 2],     ov1 = Os[cur][k][tx * 2 + 1];
            acc[0][0] = fmaf(fv0, ov0, acc[0][0]);
            acc[0][1] = fmaf(fv0, ov1, acc[0][1]);
            acc[1][0] = fmaf(fv1, ov0, acc[1][0]);
            acc[1][1] = fmaf(fv1, ov1, acc[1][1]);
        }
        __syncthreads();
    }
    float g = gamma[0];
#pragma unroll
    for (int i = 0; i < 2; i++)
#pragma unroll
        for (int j = 0; j < 2; j++)
            g_weff[(f0 + ty * 2 + i) * NC + c0 + tx * 2 + j] = g * acc[i][j];
}

// ---------------- kernel P2: A_full -> fp16 (8 f-rows per block; attn staged once) ----------------
__global__ __launch_bounds__(512) void afull_kernel(const float* __restrict__ fusion_w)
{
    __shared__ float at[NHEADS * NCH * NCH];   // 32 KB
    __shared__ float wr[8 * NC];               // 8 KB

    int b  = blockIdx.x >> 5;
    int fg = (blockIdx.x & 31) * 8;
    int tid = threadIdx.x;

    const float* ab = g_attn + (size_t)b * NHEADS * NCH * NCH;
#pragma unroll
    for (int r = 0; r < 16; r++)
        at[tid + r * 512] = ab[tid + r * 512];
#pragma unroll
    for (int r = 0; r < 4; r++)
        wr[tid + r * 512] = g_weff[(size_t)fg * NC + tid + r * 512];
    __syncthreads();

    int col = tid;
    if (col < NC) {
        int h = col >> 5, d = col & 31;
        const float* arow = at + (size_t)h * NCH * NCH + d;
#pragma unroll
        for (int fi = 0; fi < 8; fi++) {
            const float* wrow = wr + fi * NC + h * NCH;
            float s = 0.f;
#pragma unroll
            for (int cc = 0; cc < NCH; cc++)
                s = fmaf(wrow[cc], arow[cc * NCH], s);
            g_af[((size_t)(b * NC + fg + fi)) * (2 * NC) + col] = __float2half_rn(s);
        }
    } else {
#pragma unroll
        for (int fi = 0; fi < 8; fi++) {
            float v = fusion_w[(size_t)(fg + fi) * (2 * NC) + col];
            g_af[((size_t)(b * NC + fg + fi)) * (2 * NC) + col] = __float2half_rn(v);
        }
    }
}

// ---------------- kernel 4: main GEMM — fp16 HMMA, cp.async 2-stage, BK=64 ----------------
#define AP 72     // A smem pitch (halves): 144B rows -> conflict-free ldmatrix
#define BP 136    // B smem pitch (halves): 272B rows -> conflict-free ldmatrix.trans
__global__ __launch_bounds__(256, 2) void main_gemm(float* __restrict__ y)
{
    __shared__ __align__(128) __half As[2][128][AP];
    __shared__ __align__(128) __half Bs[2][64][BP];

    int b  = blockIdx.z;
    int m0 = blockIdx.y * 128;
    int n0 = blockIdx.x * 128;
    int tid  = threadIdx.x;
    int lane = tid & 31;
    int warp = tid >> 5;
    int wm = (warp >> 2) * 64;
    int wn = (warp & 3) * 32;
    int g = lane >> 2;
    int t = lane & 3;

    int lr = lane & 15;
    int lc = (lane >> 4) * 8;

    const __half* gA = g_af + (size_t)(b * NC + m0) * (2 * NC);

    float acc[4][4][4];
#pragma unroll
    for (int i = 0; i < 4; i++)
#pragma unroll
        for (int j = 0; j < 4; j++)
#pragma unroll
            for (int r = 0; r < 4; r++) acc[i][j][r] = 0.f;

    auto load_stage = [&](int s, int it) {
        int k0 = it * 64;
#pragma unroll
        for (int c = 0; c < 4; c++) {
            int id = tid + c * 256;
            int row = id >> 3;
            int kc = (id & 7) * 8;
            cpa16(&As[s][row][kc], gA + (size_t)row * (2 * NC) + k0 + kc);
        }
#pragma unroll
        for (int c = 0; c < 4; c++) {
            int id = tid + c * 256;
            int krow = id >> 4;
            int nc = (id & 15) * 8;
            int grow = k0 + krow;
            const __half* src = (grow < NC)
                ? g_vf + (size_t)(b * NC + grow) * NPIX + n0 + nc
                : g_xf + (size_t)(b * NC + grow - NC) * NPIX + n0 + nc;
            cpa16(&Bs[s][krow][nc], src);
        }
        asm volatile("cp.async.commit_group;");
    };

    load_stage(0, 0);

    const int NIT = (2 * NC) / 64;   // 8
    for (int it = 0; it < NIT; it++) {
        int cur = it & 1;
        if (it + 1 < NIT) {
            load_stage(cur ^ 1, it + 1);
            asm volatile("cp.async.wait_group 1;");
        } else {
            asm volatile("cp.async.wait_group 0;");
        }
        __syncthreads();

#pragma unroll
        for (int ks = 0; ks < 4; ks++) {
            int kof = ks * 16;
            unsigned bh[4][2];
#pragma unroll
            for (int nb = 0; nb < 2; nb++) {
                unsigned d0, d1, d2, d3;
                ldsm4t(d0, d1, d2, d3, &Bs[cur][kof + lr][wn + nb * 16 + lc]);
                bh[nb * 2][0] = d0; bh[nb * 2][1] = d1;
                bh[nb * 2 + 1][0] = d2; bh[nb * 2 + 1][1] = d3;
            }
            unsigned af[4][4];
#pragma unroll
            for (int mf = 0; mf < 4; mf++)
                ldsm4(af[mf][0], af[mf][1], af[mf][2], af[mf][3],
                      &As[cur][wm + mf * 16 + lr][kof + lc]);
#pragma unroll
            for (int nf = 0; nf < 4; nf++)
#pragma unroll
                for (int mf = 0; mf < 4; mf++)
                    mma_f16(acc[mf][nf], af[mf], bh[nf]);
        }
        __syncthreads();
    }

#pragma unroll
    for (int mf = 0; mf < 4; mf++) {
        int m = m0 + wm + mf * 16 + g;
        float be0 = g_beff[m];
        float be1 = g_beff[m + 8];
        float* yr0 = y + (size_t)(b * NC + m) * NPIX + n0 + wn;
        float* yr1 = yr0 + (size_t)8 * NPIX;
#pragma unroll
        for (int nf = 0; nf < 4; nf++) {
            *(float2*)(yr0 + nf * 8 + t * 2) =
                make_float2(acc[mf][nf][0] + be0, acc[mf][nf][1] + be0);
            *(float2*)(yr1 + nf * 8 + t * 2) =
                make_float2(acc[mf][nf][2] + be1, acc[mf][nf][3] + be1);
        }
    }
}

// ---------------- launch ----------------
extern "C" void kernel_launch(void* const* d_in, const int* in_sizes, int n_in,
                              void* d_out, int out_size)
{
    const float* x        = (const float*)d_in[0];
    const float* q_w      = (const float*)d_in[1];
    const float* q_b      = (const float*)d_in[2];
    const float* k_w      = (const float*)d_in[3];
    const float* k_b      = (const float*)d_in[4];
    const float* v_w      = (const float*)d_in[5];
    const float* v_b      = (const float*)d_in[6];
    const float* out_w    = (const float*)d_in[7];
    const float* out_b    = (const float*)d_in[8];
    const float* fusion_w = (const float*)d_in[9];
    const float* fusion_b = (const float*)d_in[10];
    const float* temperature = (const float*)d_in[11];
    const float* gamma    = (const float*)d_in[12];
    float* y = (float*)d_out;

    dwconv_qkv<<<NB * NC, 256>>>(x, q_w, q_b, k_w, k_b, v_w, v_b);

    dim3 ggrid(NB * NHEADS, NSPLIT);
    gram_tc<<<ggrid, 128>>>();

    mid_kernel<<<96, 256>>>(temperature, fusion_w, out_w, out_b, fusion_b, gamma);

    afull_kernel<<<NB * 32, 512>>>(fusion_w);

    dim3 mgrid(NPIX / 128, NC / 128, NB);
    main_gemm<<<mgrid, 256>>>(y);
}